// round 13
// baseline (speedup 1.0000x reference)
#include <cuda_runtime.h>
#include <cuda_bf16.h>
#include <cuda_fp16.h>
#include <cstdint>

#define NN 100000
#define EE 1000000
#define DD 64

// ---------------- device scratch ----------------
__device__ int      g_deg[NN];
__device__ int      g_cursor[NN];
__device__ int      g_rowptr[NN + 1];
__device__ int      g_bsum[128];
__device__ int      g_csrc[EE];
__device__ float    g_invdeg[NN];
__device__ float    g_h[NN * DD];
__device__ __half   g_p[NN * DD];      // fp16: gathered lin_l partials (halves L2 gather traffic)
__device__ float    g_tmp[NN * DD];
// W' in fragment-major fp16 layout: per layer 64 fragment-groups x 32 lanes of uint2
__device__ uint2    g_Wf[3 * 2048];

__device__ __forceinline__ unsigned pack_h2(float a, float b) {
    __half2 t = __floats2half2_rn(a, b);
    return *(unsigned*)&t;
}

// ---------------- CSR construction ----------------
__global__ void k_count(const int* __restrict__ dst, int e) {
    int i = blockIdx.x * blockDim.x + threadIdx.x;
    if (i < e) atomicAdd(&g_deg[__ldg(dst + i)], 1);
}

__global__ void k_scanA(int n) {
    __shared__ int wsum[32];
    int t = threadIdx.x;
    int i = blockIdx.x * 1024 + t;
    int v = (i < n) ? g_deg[i] : 0;
    int lane = t & 31, w = t >> 5;
    int s = v;
    #pragma unroll
    for (int off = 1; off < 32; off <<= 1) {
        int u = __shfl_up_sync(0xffffffffu, s, off);
        if (lane >= off) s += u;
    }
    if (lane == 31) wsum[w] = s;
    __syncthreads();
    if (w == 0) {
        int ws = wsum[lane];
        #pragma unroll
        for (int off = 1; off < 32; off <<= 1) {
            int u = __shfl_up_sync(0xffffffffu, ws, off);
            if (lane >= off) ws += u;
        }
        wsum[lane] = ws;
    }
    __syncthreads();
    int base = (w > 0) ? wsum[w - 1] : 0;
    int incl = base + s;
    if (i < n) g_rowptr[i] = incl - v;          // exclusive
    if (t == 1023) g_bsum[blockIdx.x] = incl;
}

__global__ void k_scanB(int nb) {
    __shared__ int wsum[4];
    int t = threadIdx.x;                        // 128 threads
    int lane = t & 31, w = t >> 5;
    int v = (t < nb) ? g_bsum[t] : 0;
    int s = v;
    #pragma unroll
    for (int off = 1; off < 32; off <<= 1) {
        int u = __shfl_up_sync(0xffffffffu, s, off);
        if (lane >= off) s += u;
    }
    if (lane == 31) wsum[w] = s;
    __syncthreads();
    int base = 0;
    for (int q = 0; q < w; q++) base += wsum[q];
    if (t < nb) g_bsum[t] = base + s - v;       // exclusive
}

__global__ void k_scanC(int n, int e) {
    int i = blockIdx.x * blockDim.x + threadIdx.x;
    if (i < n) {
        g_rowptr[i] += g_bsum[i >> 10];
        g_invdeg[i] = 1.0f / fmaxf((float)g_deg[i], 1.0f);
    }
    if (i == 0) g_rowptr[n] = e;
}

__global__ void k_fill(const int* __restrict__ src, const int* __restrict__ dst, int e) {
    int i = blockIdx.x * blockDim.x + threadIdx.x;
    if (i < e) {
        int d = __ldg(dst + i);
        int pos = g_rowptr[d] + atomicAdd(&g_cursor[d], 1);
        g_csrc[pos] = __ldg(src + i);
    }
}

// ---------------- W' precompute into fragment-major fp16 layout ----------------
__global__ void k_prepW(const float* __restrict__ Wr, const float* __restrict__ Wl) {
    int idx = blockIdx.x * blockDim.x + threadIdx.x;
    if (idx >= 3 * 2048) return;
    int l = idx / 2048;
    int rem = idx - l * 2048;
    int fg = rem >> 5;                 // 0..63
    int lane = rem & 31;
    int cg = fg >> 5;                  // 0..1
    int nt = (fg >> 2) & 7;            // 0..7
    int ks = fg & 3;                   // 0..3
    int c = cg * 64 + nt * 8 + (lane >> 2);
    int q = lane & 3;
    int k0 = 16 * ks + 2 * q;
    int k1 = k0 + 8;
    const float* Wsrc = (c < 64) ? (Wr + l * 4096 + c * 64) : (Wl + l * 4096 + (c - 64) * 64);
    uint2 v;
    v.x = pack_h2(__ldg(Wsrc + k0), __ldg(Wsrc + k0 + 1));
    v.y = pack_h2(__ldg(Wsrc + k1), __ldg(Wsrc + k1 + 1));
    g_Wf[idx] = v;
}

// ---------------- HMMA dual GEMM: tmp = A@Wr^T + bl ; p = A@Wl^T ----------------
// CTA tile: 64 rows x 128 cols, warp tile 16x64. A direct from global (overlaps MMA),
// W (fp16) via LDG.64 from fragment-major g_Wf (L1-resident, 16KB).
// fp16 2-term split: A = Ahi + Alo (exact residual); acc += Ahi*W + Alo*W.
// __launch_bounds__(256,4): cap regs at 64 -> 32 warps/SM for latency hiding.
#define EPS 68   // epilogue smem stride (words)

__device__ __forceinline__ void mma_f16(float* c, unsigned a0, unsigned a1, unsigned a2,
                                        unsigned a3, unsigned b0, unsigned b1) {
    asm volatile(
        "mma.sync.aligned.m16n8k16.row.col.f32.f16.f16.f32 "
        "{%0,%1,%2,%3}, {%4,%5,%6,%7}, {%8,%9}, {%0,%1,%2,%3};"
        : "+f"(c[0]), "+f"(c[1]), "+f"(c[2]), "+f"(c[3])
        : "r"(a0), "r"(a1), "r"(a2), "r"(a3), "r"(b0), "r"(b1));
}

__global__ void __launch_bounds__(256, 4) k_mma(const float* __restrict__ A,
                                                const uint2* __restrict__ Wf,
                                                const float* __restrict__ bl,
                                                float* __restrict__ tmp, __half* __restrict__ p, int n) {
    __shared__ float buf[64 * EPS];
    int tid = threadIdx.x;
    int i0 = blockIdx.x * 64;

    int w = tid >> 5, lane = tid & 31;
    int wr = (w >> 1) * 16;                   // 4 row groups
    int cg = w & 1;                           // 2 col groups
    int g = lane >> 2, q = lane & 3;

    int r0 = i0 + wr + g, r1 = r0 + 8;
    bool v0 = r0 < n, v1 = r1 < n;
    const float* A0 = A + (size_t)r0 * 64;
    const float* A1 = A + (size_t)r1 * 64;

    float acc[8][4];
    #pragma unroll
    for (int nt = 0; nt < 8; nt++)
        #pragma unroll
        for (int z = 0; z < 4; z++) acc[nt][z] = 0.f;

    const uint2* Wbase = Wf + cg * 1024 + lane;   // + ((nt*4)+ks)*32

    #pragma unroll
    for (int ks = 0; ks < 4; ks++) {
        int k0 = ks * 16 + 2 * q;
        float2 z = make_float2(0.f, 0.f);
        float2 x00 = v0 ? __ldg((const float2*)(A0 + k0))     : z;  // row r0, k0
        float2 x10 = v1 ? __ldg((const float2*)(A1 + k0))     : z;  // row r1, k0
        float2 x01 = v0 ? __ldg((const float2*)(A0 + k0 + 8)) : z;  // row r0, k0+8
        float2 x11 = v1 ? __ldg((const float2*)(A1 + k0 + 8)) : z;  // row r1, k0+8

        // fp16 2-term split of A: hi + exact residual (reuse temporaries to cap regs)
        unsigned ah0 = pack_h2(x00.x, x00.y);
        unsigned ah1 = pack_h2(x10.x, x10.y);
        unsigned ah2 = pack_h2(x01.x, x01.y);
        unsigned ah3 = pack_h2(x11.x, x11.y);
        float2 f;
        f = __half22float2(*(__half2*)&ah0);
        unsigned al0 = pack_h2(x00.x - f.x, x00.y - f.y);
        f = __half22float2(*(__half2*)&ah1);
        unsigned al1 = pack_h2(x10.x - f.x, x10.y - f.y);
        f = __half22float2(*(__half2*)&ah2);
        unsigned al2 = pack_h2(x01.x - f.x, x01.y - f.y);
        f = __half22float2(*(__half2*)&ah3);
        unsigned al3 = pack_h2(x11.x - f.x, x11.y - f.y);

        #pragma unroll
        for (int nt = 0; nt < 8; nt++) {
            uint2 b = __ldg(Wbase + (nt * 4 + ks) * 32);
            mma_f16(acc[nt], ah0, ah1, ah2, ah3, b.x, b.y);   // hi * W
            mma_f16(acc[nt], al0, al1, al2, al3, b.x, b.y);   // lo * W
        }
    }

    int lr0 = wr + g, lr1 = lr0 + 8;          // local rows

    // pass 0: tmp (fp32, + bias), staged through smem, coalesced float4 stores
    if (cg == 0) {
        #pragma unroll
        for (int nt = 0; nt < 8; nt++) {
            int cl = nt * 8 + 2 * q;
            float b0 = __ldg(bl + cl), b1 = __ldg(bl + cl + 1);
            *(float2*)(buf + lr0 * EPS + cl) = make_float2(acc[nt][0] + b0, acc[nt][1] + b1);
            *(float2*)(buf + lr1 * EPS + cl) = make_float2(acc[nt][2] + b0, acc[nt][3] + b1);
        }
    }
    __syncthreads();
    for (int idx = tid; idx < 1024; idx += 256) {
        int row = idx >> 4, c4 = idx & 15;
        int gr = i0 + row;
        if (gr < n)
            *(float4*)(tmp + (size_t)gr * 64 + c4 * 4) = *(float4*)(buf + row * EPS + c4 * 4);
    }
    __syncthreads();

    // pass 1: p (fp16), packed half2 words staged through smem, coalesced uint4 stores
    unsigned* ubuf = (unsigned*)buf;
    if (cg == 1) {
        #pragma unroll
        for (int nt = 0; nt < 8; nt++) {
            int wi = nt * 4 + q;              // half2 word index 0..31
            ubuf[lr0 * EPS + wi] = pack_h2(acc[nt][0], acc[nt][1]);
            ubuf[lr1 * EPS + wi] = pack_h2(acc[nt][2], acc[nt][3]);
        }
    }
    __syncthreads();
    for (int idx = tid; idx < 512; idx += 256) {
        int row = idx >> 3, c8 = idx & 7;     // 8 halves per uint4
        int gr = i0 + row;
        if (gr < n)
            *(uint4*)(p + (size_t)gr * 64 + c8 * 8) = *(uint4*)(ubuf + row * EPS + c8 * 4);
    }
}

// ---------------- aggregation: h[i] = relu(tmp[i] + invdeg[i] * sum p[src]) ----------------
__global__ void k_aggr(const __half* __restrict__ p, const float* __restrict__ tmp,
                       float* __restrict__ h, int n) {
    int gw = (blockIdx.x * blockDim.x + threadIdx.x) >> 5;
    int lane = threadIdx.x & 31;
    if (gw >= n) return;
    int s = __ldg(g_rowptr + gw), eend = __ldg(g_rowptr + gw + 1);
    const __half2* P = (const __half2*)p;
    float ax = 0.f, ay = 0.f, bx = 0.f, by = 0.f;
    int e = s;
    for (; e + 3 < eend; e += 4) {
        int s0 = __ldg(g_csrc + e),     s1 = __ldg(g_csrc + e + 1);
        int s2 = __ldg(g_csrc + e + 2), s3 = __ldg(g_csrc + e + 3);
        float2 v0 = __half22float2(__ldg(P + s0 * 32 + lane));
        float2 v1 = __half22float2(__ldg(P + s1 * 32 + lane));
        float2 v2 = __half22float2(__ldg(P + s2 * 32 + lane));
        float2 v3 = __half22float2(__ldg(P + s3 * 32 + lane));
        ax += v0.x; ay += v0.y; bx += v1.x; by += v1.y;
        ax += v2.x; ay += v2.y; bx += v3.x; by += v3.y;
    }
    for (; e < eend; e++) {
        int s0 = __ldg(g_csrc + e);
        float2 v0 = __half22float2(__ldg(P + s0 * 32 + lane));
        ax += v0.x; ay += v0.y;
    }
    float id = __ldg(g_invdeg + gw);
    float2 t = __ldg((const float2*)tmp + gw * 32 + lane);
    float rx = fmaxf(t.x + id * (ax + bx), 0.f);
    float ry = fmaxf(t.y + id * (ay + by), 0.f);
    ((float2*)h)[gw * 32 + lane] = make_float2(rx, ry);
}

// ---------------- final layer: aggregation fused with classifier head ----------------
__global__ void k_aggr_out(const __half* __restrict__ p, const float* __restrict__ tmp,
                           const float* __restrict__ Wout, const float* __restrict__ bout,
                           float* __restrict__ out, int n) {
    int gw = (blockIdx.x * blockDim.x + threadIdx.x) >> 5;
    int lane = threadIdx.x & 31;
    if (gw >= n) return;
    int s = __ldg(g_rowptr + gw), eend = __ldg(g_rowptr + gw + 1);
    const __half2* P = (const __half2*)p;
    float ax = 0.f, ay = 0.f, bx = 0.f, by = 0.f;
    int e = s;
    for (; e + 3 < eend; e += 4) {
        int s0 = __ldg(g_csrc + e),     s1 = __ldg(g_csrc + e + 1);
        int s2 = __ldg(g_csrc + e + 2), s3 = __ldg(g_csrc + e + 3);
        float2 v0 = __half22float2(__ldg(P + s0 * 32 + lane));
        float2 v1 = __half22float2(__ldg(P + s1 * 32 + lane));
        float2 v2 = __half22float2(__ldg(P + s2 * 32 + lane));
        float2 v3 = __half22float2(__ldg(P + s3 * 32 + lane));
        ax += v0.x; ay += v0.y; bx += v1.x; by += v1.y;
        ax += v2.x; ay += v2.y; bx += v3.x; by += v3.y;
    }
    for (; e < eend; e++) {
        int s0 = __ldg(g_csrc + e);
        float2 v0 = __half22float2(__ldg(P + s0 * 32 + lane));
        ax += v0.x; ay += v0.y;
    }
    float id = __ldg(g_invdeg + gw);
    float2 t = __ldg((const float2*)tmp + gw * 32 + lane);
    float rx = t.x + id * (ax + bx);
    float ry = t.y + id * (ay + by);
    float o0 = rx * __ldg(Wout + 2 * lane)      + ry * __ldg(Wout + 2 * lane + 1);
    float o1 = rx * __ldg(Wout + 64 + 2 * lane) + ry * __ldg(Wout + 64 + 2 * lane + 1);
    #pragma unroll
    for (int off = 16; off; off >>= 1) {
        o0 += __shfl_down_sync(0xffffffffu, o0, off);
        o1 += __shfl_down_sync(0xffffffffu, o1, off);
    }
    if (lane == 0) {
        out[gw * 2 + 0] = o0 + __ldg(bout + 0);
        out[gw * 2 + 1] = o1 + __ldg(bout + 1);
    }
}

// ---------------- launch: fork-join overlap of CSR build with layer-0 GEMM ----------------
extern "C" void kernel_launch(void* const* d_in, const int* in_sizes, int n_in,
                              void* d_out, int out_size) {
    const float* x    = (const float*)d_in[0];
    const int*   ei   = (const int*)d_in[1];
    const float* Wl   = (const float*)d_in[2];
    const float* bl   = (const float*)d_in[3];
    const float* Wr   = (const float*)d_in[4];
    const float* Wout = (const float*)d_in[5];
    const float* bout = (const float*)d_in[6];
    float* out = (float*)d_out;

    int n = in_sizes[0] / DD;
    int e = in_sizes[1] / 2;
    const int* src = ei;
    const int* dst = ei + e;

    float *hP, *tP;
    __half* pP;
    uint2* WfP;
    int *degP, *curP;
    cudaGetSymbolAddress((void**)&hP, g_h);
    cudaGetSymbolAddress((void**)&pP, g_p);
    cudaGetSymbolAddress((void**)&tP, g_tmp);
    cudaGetSymbolAddress((void**)&WfP, g_Wf);
    cudaGetSymbolAddress((void**)&degP, g_deg);
    cudaGetSymbolAddress((void**)&curP, g_cursor);

    int nb = (n + 1023) / 1024;
    int mma_blocks = (n + 63) / 64;
    int warp_blocks = (n + 7) / 8;

    cudaStream_t s1;
    cudaStreamCreateWithFlags(&s1, cudaStreamNonBlocking);
    cudaEvent_t evFork, evJoin;
    cudaEventCreateWithFlags(&evFork, cudaEventDisableTiming);
    cudaEventCreateWithFlags(&evJoin, cudaEventDisableTiming);

    // fork: side stream builds CSR while main stream does weights + layer-0 GEMM
    cudaEventRecord(evFork, 0);
    cudaStreamWaitEvent(s1, evFork, 0);

    cudaMemsetAsync(degP, 0, (size_t)n * sizeof(int), s1);
    cudaMemsetAsync(curP, 0, (size_t)n * sizeof(int), s1);
    k_prepW<<<(3 * 2048 + 255) / 256, 256>>>(Wr, Wl);                     // main
    k_count<<<(e + 255) / 256, 256, 0, s1>>>(dst, e);                     // side
    k_scanA<<<nb, 1024, 0, s1>>>(n);                                      // side
    k_mma<<<mma_blocks, 256>>>(x, WfP, bl, tP, pP, n);                    // main; ncu slot
    k_scanB<<<1, 128, 0, s1>>>(nb);                                       // side
    k_scanC<<<(n + 255) / 256, 256, 0, s1>>>(n, e);                       // side
    k_fill<<<(e + 255) / 256, 256, 0, s1>>>(src, dst, e);                 // side
    cudaEventRecord(evJoin, s1);

    // join: aggregation needs both CSR (side) and GEMM outputs (main)
    cudaStreamWaitEvent(0, evJoin, 0);
    k_aggr<<<warp_blocks, 256>>>(pP, tP, hP, n);

    k_mma<<<mma_blocks, 256>>>(hP, WfP + 2048, bl + 64, tP, pP, n);
    k_aggr<<<warp_blocks, 256>>>(pP, tP, hP, n);

    k_mma<<<mma_blocks, 256>>>(hP, WfP + 4096, bl + 128, tP, pP, n);
    k_aggr_out<<<warp_blocks, 256>>>(pP, tP, Wout, bout, out, n);

    cudaEventDestroy(evFork);
    cudaEventDestroy(evJoin);
    cudaStreamDestroy(s1);
}

// round 14
// speedup vs baseline: 1.0444x; 1.0444x over previous
#include <cuda_runtime.h>
#include <cuda_bf16.h>
#include <cuda_fp16.h>
#include <cstdint>

#define NN 100000
#define EE 1000000
#define DD 64

// ---------------- device scratch ----------------
__device__ int      g_deg[NN];
__device__ int      g_cursor[NN];
__device__ int      g_rowptr[NN + 1];
__device__ int      g_bsum[128];
__device__ int      g_csrc[EE];
__device__ float    g_invdeg[NN];
__device__ float    g_h[NN * DD];
__device__ __half   g_p[NN * DD];      // fp16: gathered lin_l partials
__device__ float    g_tmp[NN * DD];
// W' in fragment-major fp16 layout: per layer 64 fragment-groups x 32 lanes of uint2
__device__ uint2    g_Wf[3 * 2048];

__device__ __forceinline__ unsigned pack_h2(float a, float b) {
    __half2 t = __floats2half2_rn(a, b);
    return *(unsigned*)&t;
}
__device__ __forceinline__ float4 h4_to_f4(uint2 v) {
    float2 a = __half22float2(*(__half2*)&v.x);
    float2 b = __half22float2(*(__half2*)&v.y);
    return make_float4(a.x, a.y, b.x, b.y);
}

// ---------------- CSR construction ----------------
__global__ void k_count(const int* __restrict__ dst, int e) {
    int i = blockIdx.x * blockDim.x + threadIdx.x;
    if (i < e) atomicAdd(&g_deg[__ldg(dst + i)], 1);
}

__global__ void k_scanA(int n) {
    __shared__ int wsum[32];
    int t = threadIdx.x;
    int i = blockIdx.x * 1024 + t;
    int v = (i < n) ? g_deg[i] : 0;
    int lane = t & 31, w = t >> 5;
    int s = v;
    #pragma unroll
    for (int off = 1; off < 32; off <<= 1) {
        int u = __shfl_up_sync(0xffffffffu, s, off);
        if (lane >= off) s += u;
    }
    if (lane == 31) wsum[w] = s;
    __syncthreads();
    if (w == 0) {
        int ws = wsum[lane];
        #pragma unroll
        for (int off = 1; off < 32; off <<= 1) {
            int u = __shfl_up_sync(0xffffffffu, ws, off);
            if (lane >= off) ws += u;
        }
        wsum[lane] = ws;
    }
    __syncthreads();
    int base = (w > 0) ? wsum[w - 1] : 0;
    int incl = base + s;
    if (i < n) g_rowptr[i] = incl - v;          // exclusive
    if (t == 1023) g_bsum[blockIdx.x] = incl;
}

__global__ void k_scanB(int nb) {
    __shared__ int wsum[4];
    int t = threadIdx.x;                        // 128 threads
    int lane = t & 31, w = t >> 5;
    int v = (t < nb) ? g_bsum[t] : 0;
    int s = v;
    #pragma unroll
    for (int off = 1; off < 32; off <<= 1) {
        int u = __shfl_up_sync(0xffffffffu, s, off);
        if (lane >= off) s += u;
    }
    if (lane == 31) wsum[w] = s;
    __syncthreads();
    int base = 0;
    for (int q = 0; q < w; q++) base += wsum[q];
    if (t < nb) g_bsum[t] = base + s - v;       // exclusive
}

__global__ void k_scanC(int n, int e) {
    int i = blockIdx.x * blockDim.x + threadIdx.x;
    if (i < n) {
        g_rowptr[i] += g_bsum[i >> 10];
        g_invdeg[i] = 1.0f / fmaxf((float)g_deg[i], 1.0f);
    }
    if (i == 0) g_rowptr[n] = e;
}

__global__ void k_fill(const int* __restrict__ src, const int* __restrict__ dst, int e) {
    int i = blockIdx.x * blockDim.x + threadIdx.x;
    if (i < e) {
        int d = __ldg(dst + i);
        int pos = g_rowptr[d] + atomicAdd(&g_cursor[d], 1);
        g_csrc[pos] = __ldg(src + i);
    }
}

// ---------------- W' precompute into fragment-major fp16 layout ----------------
__global__ void k_prepW(const float* __restrict__ Wr, const float* __restrict__ Wl) {
    int idx = blockIdx.x * blockDim.x + threadIdx.x;
    if (idx >= 3 * 2048) return;
    int l = idx / 2048;
    int rem = idx - l * 2048;
    int fg = rem >> 5;                 // 0..63
    int lane = rem & 31;
    int cg = fg >> 5;                  // 0..1
    int nt = (fg >> 2) & 7;            // 0..7
    int ks = fg & 3;                   // 0..3
    int c = cg * 64 + nt * 8 + (lane >> 2);
    int q = lane & 3;
    int k0 = 16 * ks + 2 * q;
    int k1 = k0 + 8;
    const float* Wsrc = (c < 64) ? (Wr + l * 4096 + c * 64) : (Wl + l * 4096 + (c - 64) * 64);
    uint2 v;
    v.x = pack_h2(__ldg(Wsrc + k0), __ldg(Wsrc + k0 + 1));
    v.y = pack_h2(__ldg(Wsrc + k1), __ldg(Wsrc + k1 + 1));
    g_Wf[idx] = v;
}

// ---------------- HMMA dual GEMM (R12 config): tmp = A@Wr^T + bl ; p = A@Wl^T ----------------
#define EPS 68   // epilogue smem stride (words)

__device__ __forceinline__ void mma_f16(float* c, unsigned a0, unsigned a1, unsigned a2,
                                        unsigned a3, unsigned b0, unsigned b1) {
    asm volatile(
        "mma.sync.aligned.m16n8k16.row.col.f32.f16.f16.f32 "
        "{%0,%1,%2,%3}, {%4,%5,%6,%7}, {%8,%9}, {%0,%1,%2,%3};"
        : "+f"(c[0]), "+f"(c[1]), "+f"(c[2]), "+f"(c[3])
        : "r"(a0), "r"(a1), "r"(a2), "r"(a3), "r"(b0), "r"(b1));
}

__global__ void __launch_bounds__(256, 3) k_mma(const float* __restrict__ A,
                                                const uint2* __restrict__ Wf,
                                                const float* __restrict__ bl,
                                                float* __restrict__ tmp, __half* __restrict__ p, int n) {
    __shared__ float buf[64 * EPS];
    int tid = threadIdx.x;
    int i0 = blockIdx.x * 64;

    int w = tid >> 5, lane = tid & 31;
    int wr = (w >> 1) * 16;                   // 4 row groups
    int cg = w & 1;                           // 2 col groups
    int g = lane >> 2, q = lane & 3;

    int r0 = i0 + wr + g, r1 = r0 + 8;
    bool v0 = r0 < n, v1 = r1 < n;
    const float* A0 = A + (size_t)r0 * 64;
    const float* A1 = A + (size_t)r1 * 64;

    float acc[8][4];
    #pragma unroll
    for (int nt = 0; nt < 8; nt++)
        #pragma unroll
        for (int z = 0; z < 4; z++) acc[nt][z] = 0.f;

    const uint2* Wbase = Wf + cg * 1024 + lane;   // + ((nt*4)+ks)*32

    #pragma unroll
    for (int ks = 0; ks < 4; ks++) {
        int k0 = ks * 16 + 2 * q;
        float2 z = make_float2(0.f, 0.f);
        float2 x00 = v0 ? __ldg((const float2*)(A0 + k0))     : z;
        float2 x10 = v1 ? __ldg((const float2*)(A1 + k0))     : z;
        float2 x01 = v0 ? __ldg((const float2*)(A0 + k0 + 8)) : z;
        float2 x11 = v1 ? __ldg((const float2*)(A1 + k0 + 8)) : z;

        unsigned ah0 = pack_h2(x00.x, x00.y);
        unsigned ah1 = pack_h2(x10.x, x10.y);
        unsigned ah2 = pack_h2(x01.x, x01.y);
        unsigned ah3 = pack_h2(x11.x, x11.y);
        float2 f0 = __half22float2(*(__half2*)&ah0);
        float2 f1 = __half22float2(*(__half2*)&ah1);
        float2 f2 = __half22float2(*(__half2*)&ah2);
        float2 f3 = __half22float2(*(__half2*)&ah3);
        unsigned al0 = pack_h2(x00.x - f0.x, x00.y - f0.y);
        unsigned al1 = pack_h2(x10.x - f1.x, x10.y - f1.y);
        unsigned al2 = pack_h2(x01.x - f2.x, x01.y - f2.y);
        unsigned al3 = pack_h2(x11.x - f3.x, x11.y - f3.y);

        #pragma unroll
        for (int nt = 0; nt < 8; nt++) {
            uint2 b = __ldg(Wbase + (nt * 4 + ks) * 32);
            mma_f16(acc[nt], ah0, ah1, ah2, ah3, b.x, b.y);   // hi * W
            mma_f16(acc[nt], al0, al1, al2, al3, b.x, b.y);   // lo * W
        }
    }

    int lr0 = wr + g, lr1 = lr0 + 8;          // local rows

    // pass 0: tmp (fp32, + bias), staged through smem, coalesced float4 stores
    if (cg == 0) {
        #pragma unroll
        for (int nt = 0; nt < 8; nt++) {
            int cl = nt * 8 + 2 * q;
            float b0 = __ldg(bl + cl), b1 = __ldg(bl + cl + 1);
            *(float2*)(buf + lr0 * EPS + cl) = make_float2(acc[nt][0] + b0, acc[nt][1] + b1);
            *(float2*)(buf + lr1 * EPS + cl) = make_float2(acc[nt][2] + b0, acc[nt][3] + b1);
        }
    }
    __syncthreads();
    for (int idx = tid; idx < 1024; idx += 256) {
        int row = idx >> 4, c4 = idx & 15;
        int gr = i0 + row;
        if (gr < n)
            *(float4*)(tmp + (size_t)gr * 64 + c4 * 4) = *(float4*)(buf + row * EPS + c4 * 4);
    }
    __syncthreads();

    // pass 1: p (fp16), packed half2 words staged through smem, coalesced uint4 stores
    unsigned* ubuf = (unsigned*)buf;
    if (cg == 1) {
        #pragma unroll
        for (int nt = 0; nt < 8; nt++) {
            int wi = nt * 4 + q;              // half2 word index 0..31
            ubuf[lr0 * EPS + wi] = pack_h2(acc[nt][0], acc[nt][1]);
            ubuf[lr1 * EPS + wi] = pack_h2(acc[nt][2], acc[nt][3]);
        }
    }
    __syncthreads();
    for (int idx = tid; idx < 512; idx += 256) {
        int row = idx >> 3, c8 = idx & 7;     // 8 halves per uint4
        int gr = i0 + row;
        if (gr < n)
            *(uint4*)(p + (size_t)gr * 64 + c8 * 8) = *(uint4*)(ubuf + row * EPS + c8 * 4);
    }
}

// ---------------- aggregation (restructured): 2 edges per gather instruction ----------------
// Warp = 1 node. Lane half (lane>>4) selects edge of the pair; sub (lane&15) covers
// 4 halves (uint2 = 8B, 16 lanes = full 128B row). Combine halves via shfl_xor(16).
__global__ void k_aggr(const __half* __restrict__ p, const float* __restrict__ tmp,
                       float* __restrict__ h, int n) {
    int gw = (blockIdx.x * blockDim.x + threadIdx.x) >> 5;
    int lane = threadIdx.x & 31;
    if (gw >= n) return;
    int half = lane >> 4, sub = lane & 15;
    int s = __ldg(g_rowptr + gw), eend = __ldg(g_rowptr + gw + 1);
    const uint2* P2 = (const uint2*)p;        // row stride 16 uint2
    float ax = 0.f, ay = 0.f, az = 0.f, aw = 0.f;
    int e = s;
    for (; e + 3 < eend; e += 4) {            // 4 edges: 2 pair-gathers in flight
        int r0 = __ldg(g_csrc + e + half);
        int r1 = __ldg(g_csrc + e + 2 + half);
        float4 u0 = h4_to_f4(__ldg(P2 + r0 * 16 + sub));
        float4 u1 = h4_to_f4(__ldg(P2 + r1 * 16 + sub));
        ax += u0.x + u1.x; ay += u0.y + u1.y;
        az += u0.z + u1.z; aw += u0.w + u1.w;
    }
    for (; e + 1 < eend; e += 2) {            // one pair
        int r0 = __ldg(g_csrc + e + half);
        float4 u0 = h4_to_f4(__ldg(P2 + r0 * 16 + sub));
        ax += u0.x; ay += u0.y; az += u0.z; aw += u0.w;
    }
    if (e < eend && half == 0) {              // single leftover edge (half 0 only)
        int r0 = __ldg(g_csrc + e);
        float4 u0 = h4_to_f4(__ldg(P2 + r0 * 16 + sub));
        ax += u0.x; ay += u0.y; az += u0.z; aw += u0.w;
    }
    // combine the two halves (column sets identical across halves)
    ax += __shfl_xor_sync(0xffffffffu, ax, 16);
    ay += __shfl_xor_sync(0xffffffffu, ay, 16);
    az += __shfl_xor_sync(0xffffffffu, az, 16);
    aw += __shfl_xor_sync(0xffffffffu, aw, 16);
    if (half == 0) {
        float id = __ldg(g_invdeg + gw);
        float4 t = __ldg((const float4*)tmp + gw * 16 + sub);
        float4 r;
        r.x = fmaxf(t.x + id * ax, 0.f);
        r.y = fmaxf(t.y + id * ay, 0.f);
        r.z = fmaxf(t.z + id * az, 0.f);
        r.w = fmaxf(t.w + id * aw, 0.f);
        ((float4*)h)[gw * 16 + sub] = r;
    }
}

// ---------------- final layer: aggregation (restructured) fused with classifier head ----------------
__global__ void k_aggr_out(const __half* __restrict__ p, const float* __restrict__ tmp,
                           const float* __restrict__ Wout, const float* __restrict__ bout,
                           float* __restrict__ out, int n) {
    int gw = (blockIdx.x * blockDim.x + threadIdx.x) >> 5;
    int lane = threadIdx.x & 31;
    if (gw >= n) return;
    int half = lane >> 4, sub = lane & 15;
    int s = __ldg(g_rowptr + gw), eend = __ldg(g_rowptr + gw + 1);
    const uint2* P2 = (const uint2*)p;
    float ax = 0.f, ay = 0.f, az = 0.f, aw = 0.f;
    int e = s;
    for (; e + 3 < eend; e += 4) {
        int r0 = __ldg(g_csrc + e + half);
        int r1 = __ldg(g_csrc + e + 2 + half);
        float4 u0 = h4_to_f4(__ldg(P2 + r0 * 16 + sub));
        float4 u1 = h4_to_f4(__ldg(P2 + r1 * 16 + sub));
        ax += u0.x + u1.x; ay += u0.y + u1.y;
        az += u0.z + u1.z; aw += u0.w + u1.w;
    }
    for (; e + 1 < eend; e += 2) {
        int r0 = __ldg(g_csrc + e + half);
        float4 u0 = h4_to_f4(__ldg(P2 + r0 * 16 + sub));
        ax += u0.x; ay += u0.y; az += u0.z; aw += u0.w;
    }
    if (e < eend && half == 0) {
        int r0 = __ldg(g_csrc + e);
        float4 u0 = h4_to_f4(__ldg(P2 + r0 * 16 + sub));
        ax += u0.x; ay += u0.y; az += u0.z; aw += u0.w;
    }
    ax += __shfl_xor_sync(0xffffffffu, ax, 16);
    ay += __shfl_xor_sync(0xffffffffu, ay, 16);
    az += __shfl_xor_sync(0xffffffffu, az, 16);
    aw += __shfl_xor_sync(0xffffffffu, aw, 16);

    float o0 = 0.f, o1 = 0.f;
    if (half == 0) {
        float id = __ldg(g_invdeg + gw);
        float4 t = __ldg((const float4*)tmp + gw * 16 + sub);
        float rx = t.x + id * ax, ry = t.y + id * ay;
        float rz = t.z + id * az, rw = t.w + id * aw;
        float4 w0 = __ldg((const float4*)Wout + sub);          // Wout[0][4sub..]
        float4 w1 = __ldg((const float4*)(Wout + 64) + sub);   // Wout[1][4sub..]
        o0 = rx * w0.x + ry * w0.y + rz * w0.z + rw * w0.w;
        o1 = rx * w1.x + ry * w1.y + rz * w1.z + rw * w1.w;
    }
    // reduce over the 16 low lanes (lane0 chain only touches lanes < 16)
    #pragma unroll
    for (int off = 8; off; off >>= 1) {
        o0 += __shfl_down_sync(0xffffffffu, o0, off);
        o1 += __shfl_down_sync(0xffffffffu, o1, off);
    }
    if (lane == 0) {
        out[gw * 2 + 0] = o0 + __ldg(bout + 0);
        out[gw * 2 + 1] = o1 + __ldg(bout + 1);
    }
}

// ---------------- launch: fork-join overlap of CSR build with layer-0 GEMM ----------------
extern "C" void kernel_launch(void* const* d_in, const int* in_sizes, int n_in,
                              void* d_out, int out_size) {
    const float* x    = (const float*)d_in[0];
    const int*   ei   = (const int*)d_in[1];
    const float* Wl   = (const float*)d_in[2];
    const float* bl   = (const float*)d_in[3];
    const float* Wr   = (const float*)d_in[4];
    const float* Wout = (const float*)d_in[5];
    const float* bout = (const float*)d_in[6];
    float* out = (float*)d_out;

    int n = in_sizes[0] / DD;
    int e = in_sizes[1] / 2;
    const int* src = ei;
    const int* dst = ei + e;

    float *hP, *tP;
    __half* pP;
    uint2* WfP;
    int *degP, *curP;
    cudaGetSymbolAddress((void**)&hP, g_h);
    cudaGetSymbolAddress((void**)&pP, g_p);
    cudaGetSymbolAddress((void**)&tP, g_tmp);
    cudaGetSymbolAddress((void**)&WfP, g_Wf);
    cudaGetSymbolAddress((void**)&degP, g_deg);
    cudaGetSymbolAddress((void**)&curP, g_cursor);

    int nb = (n + 1023) / 1024;
    int mma_blocks = (n + 63) / 64;
    int warp_blocks = (n + 7) / 8;

    cudaStream_t s1;
    cudaStreamCreateWithFlags(&s1, cudaStreamNonBlocking);
    cudaEvent_t evFork, evJoin;
    cudaEventCreateWithFlags(&evFork, cudaEventDisableTiming);
    cudaEventCreateWithFlags(&evJoin, cudaEventDisableTiming);

    // fork: side stream builds CSR while main stream does weights + layer-0 GEMM
    cudaEventRecord(evFork, 0);
    cudaStreamWaitEvent(s1, evFork, 0);

    cudaMemsetAsync(degP, 0, (size_t)n * sizeof(int), s1);
    cudaMemsetAsync(curP, 0, (size_t)n * sizeof(int), s1);
    k_prepW<<<(3 * 2048 + 255) / 256, 256>>>(Wr, Wl);                     // main
    k_count<<<(e + 255) / 256, 256, 0, s1>>>(dst, e);                     // side
    k_scanA<<<nb, 1024, 0, s1>>>(n);                                      // side
    k_mma<<<mma_blocks, 256>>>(x, WfP, bl, tP, pP, n);                    // main; ncu slot
    k_scanB<<<1, 128, 0, s1>>>(nb);                                       // side
    k_scanC<<<(n + 255) / 256, 256, 0, s1>>>(n, e);                       // side
    k_fill<<<(e + 255) / 256, 256, 0, s1>>>(src, dst, e);                 // side
    cudaEventRecord(evJoin, s1);

    // join: aggregation needs both CSR (side) and GEMM outputs (main)
    cudaStreamWaitEvent(0, evJoin, 0);
    k_aggr<<<warp_blocks, 256>>>(pP, tP, hP, n);

    k_mma<<<mma_blocks, 256>>>(hP, WfP + 2048, bl + 64, tP, pP, n);
    k_aggr<<<warp_blocks, 256>>>(pP, tP, hP, n);

    k_mma<<<mma_blocks, 256>>>(hP, WfP + 4096, bl + 128, tP, pP, n);
    k_aggr_out<<<warp_blocks, 256>>>(pP, tP, Wout, bout, out, n);

    cudaEventDestroy(evFork);
    cudaEventDestroy(evJoin);
    cudaStreamDestroy(s1);
}